// round 4
// baseline (speedup 1.0000x reference)
#include <cuda_runtime.h>
#include <cuda_fp16.h>
#include <cuda_bf16.h>
#include <cstdint>

#define IN_FEATS 128
#define HIDDEN   256
#define NMAX     100000

// fp16 per-node projections: u = Hs@W1a + b1, v = Hd@W1b
__device__ unsigned short g_u[(size_t)NMAX * HIDDEN];
__device__ unsigned short g_v[(size_t)NMAX * HIDDEN];

// ---------------------------------------------------------------------------
// helpers
// ---------------------------------------------------------------------------
__device__ __forceinline__ uint32_t smem_u32(const void* p) {
    uint32_t a;
    asm("{ .reg .u64 t; cvta.to.shared.u64 t, %1; cvt.u32.u64 %0, t; }"
        : "=r"(a) : "l"(p));
    return a;
}

// row-local XOR swizzle: rows are 256B (128 bf16). chunk(16B) ^= (row & 7).
__device__ __forceinline__ uint32_t swz(uint32_t row, uint32_t kbyte) {
    return row * 256u + ((((kbyte >> 4) ^ (row & 7u)) << 4) | (kbyte & 15u));
}

__device__ __forceinline__ void ldsm4(uint32_t* r, uint32_t a) {
    asm volatile("ldmatrix.sync.aligned.m8n8.x4.shared.b16 {%0,%1,%2,%3}, [%4];"
                 : "=r"(r[0]), "=r"(r[1]), "=r"(r[2]), "=r"(r[3]) : "r"(a));
}

__device__ __forceinline__ void mma16816(float* d, const uint32_t* a,
                                         const uint32_t* b) {
    asm volatile(
        "mma.sync.aligned.m16n8k16.row.col.f32.bf16.bf16.f32 "
        "{%0,%1,%2,%3}, {%4,%5,%6,%7}, {%8,%9}, {%0,%1,%2,%3};"
        : "+f"(d[0]), "+f"(d[1]), "+f"(d[2]), "+f"(d[3])
        : "r"(a[0]), "r"(a[1]), "r"(a[2]), "r"(a[3]), "r"(b[0]), "r"(b[1]));
}

// SMEM layout (dynamic): Ah | Al | Bh | Bl  (96KB -> 2 CTAs/SM)
static constexpr int SM_AH = 0;           // 64 rows x 256B = 16KB
static constexpr int SM_AL = 16384;
static constexpr int SM_BH = 32768;       // 128 rows x 256B = 32KB
static constexpr int SM_BL = 65536;
static constexpr int SM_TOTAL = 98304;

// ---------------------------------------------------------------------------
// Node GEMM via mma.sync: C-tile[64,128] = A[64,128] @ B[128,128]
// bf16 3-term split: Ah@Bh + Ah@Bl + Al@Bh (fp32 accum).
// 8 warps as 2(M) x 4(N); each warp 32x32.
// grid = (2 N-halves, ceil(M/64), 2 {u,v})
// ---------------------------------------------------------------------------
__global__ __launch_bounds__(256, 2)
void node_gemm_mma(const float* __restrict__ Hs,
                   const float* __restrict__ Hd,
                   const float* __restrict__ W1,
                   const float* __restrict__ b1,
                   int M)
{
    extern __shared__ char smem[];
    __shared__ float sB1[128];
    const uint32_t smb = smem_u32(smem);

    const int tid  = threadIdx.x;
    const int wid  = tid >> 5;
    const int lane = tid & 31;

    const bool is_u = (blockIdx.z == 0);
    const float* __restrict__ A  = is_u ? Hs : Hd;
    const float* __restrict__ Bg = W1 + (is_u ? 0 : (size_t)IN_FEATS * HIDDEN);
    unsigned short* __restrict__ C = is_u ? g_u : g_v;
    const int bm = blockIdx.y * 64;
    const int nh = blockIdx.x * 128;        // N-half offset

    if (tid < 128) sB1[tid] = b1[nh + tid];

    // ---- fill A (hi/lo): thread -> row tid/4, k-quarter (tid&3)*32 ----
    {
        const int row = tid >> 2;
        const int kq  = (tid & 3) * 32;
        const int grow = bm + row;
        const bool valid = grow < M;
        const float* ar = A + (size_t)grow * IN_FEATS;
        #pragma unroll
        for (int j = 0; j < 8; j++) {
            const int k = kq + j * 4;
            float4 x = valid ? *reinterpret_cast<const float4*>(ar + k)
                             : make_float4(0.f, 0.f, 0.f, 0.f);
            __nv_bfloat16 h0 = __float2bfloat16(x.x), h1 = __float2bfloat16(x.y);
            __nv_bfloat16 h2 = __float2bfloat16(x.z), h3 = __float2bfloat16(x.w);
            __nv_bfloat16 l0 = __float2bfloat16(x.x - __bfloat162float(h0));
            __nv_bfloat16 l1 = __float2bfloat16(x.y - __bfloat162float(h1));
            __nv_bfloat16 l2 = __float2bfloat16(x.z - __bfloat162float(h2));
            __nv_bfloat16 l3 = __float2bfloat16(x.w - __bfloat162float(h3));
            const uint32_t o = swz((uint32_t)row, (uint32_t)(k * 2));
            __nv_bfloat162 hv0(h0, h1), hv1(h2, h3), lv0(l0, l1), lv1(l2, l3);
            uint2 hv, lv;
            hv.x = *reinterpret_cast<uint32_t*>(&hv0);
            hv.y = *reinterpret_cast<uint32_t*>(&hv1);
            lv.x = *reinterpret_cast<uint32_t*>(&lv0);
            lv.y = *reinterpret_cast<uint32_t*>(&lv1);
            *reinterpret_cast<uint2*>(smem + SM_AH + o) = hv;
            *reinterpret_cast<uint2*>(smem + SM_AL + o) = lv;
        }
    }
    // ---- fill B (hi/lo): Bs[n][k] = Bg[k][nh+n]; coalesced over n ----
    #pragma unroll
    for (int i = 0; i < 16; i++) {
        const int linear = tid + i * 256;       // 4096 float4-groups total
        const int k  = linear >> 5;             // 32 groups per k-row
        const int n0 = (linear & 31) * 4;
        const float4 x = *reinterpret_cast<const float4*>(
            Bg + (size_t)k * HIDDEN + nh + n0);
        const float v[4] = {x.x, x.y, x.z, x.w};
        #pragma unroll
        for (int j = 0; j < 4; j++) {
            __nv_bfloat16 h = __float2bfloat16(v[j]);
            __nv_bfloat16 l = __float2bfloat16(v[j] - __bfloat162float(h));
            const uint32_t o = swz((uint32_t)(n0 + j), (uint32_t)(k * 2));
            *reinterpret_cast<__nv_bfloat16*>(smem + SM_BH + o) = h;
            *reinterpret_cast<__nv_bfloat16*>(smem + SM_BL + o) = l;
        }
    }
    __syncthreads();

    // ---- compute: warp tile 32(M) x 32(N) ----
    const int mbase = (wid >> 2) * 32;
    const int nbase = (wid & 3) * 32;

    float acc[2][4][4];
    #pragma unroll
    for (int mt = 0; mt < 2; mt++)
        #pragma unroll
        for (int nt = 0; nt < 4; nt++)
            #pragma unroll
            for (int q = 0; q < 4; q++) acc[mt][nt][q] = 0.f;

    const uint32_t rowA  = (uint32_t)(mbase + (lane & 15));
    const uint32_t xorA  = rowA & 7u;
    const uint32_t chA0  = (uint32_t)(lane >> 4);
    const uint32_t baseA = rowA * 256u;

    const uint32_t rowB  = (uint32_t)(nbase + (lane & 7) + ((lane >> 4) << 3));
    const uint32_t xorB  = rowB & 7u;
    const uint32_t chB0  = (uint32_t)((lane >> 3) & 1);
    const uint32_t baseB = rowB * 256u;

    #pragma unroll
    for (int term = 0; term < 3; term++) {
        const uint32_t aBase = smb + (term == 2 ? SM_AL : SM_AH);
        const uint32_t bBase = smb + (term == 1 ? SM_BL : SM_BH);
        #pragma unroll
        for (int ks = 0; ks < 8; ks++) {
            const uint32_t aAddr0 =
                aBase + baseA + (((chA0 + 2u * ks) ^ xorA) << 4);
            const uint32_t bAddr0 =
                bBase + baseB + (((chB0 + 2u * ks) ^ xorB) << 4);
            uint32_t af[2][4], bf[2][4];
            #pragma unroll
            for (int mt = 0; mt < 2; mt++)
                ldsm4(af[mt], aAddr0 + mt * 16 * 256);
            #pragma unroll
            for (int bt = 0; bt < 2; bt++)
                ldsm4(bf[bt], bAddr0 + bt * 16 * 256);
            #pragma unroll
            for (int mt = 0; mt < 2; mt++)
                #pragma unroll
                for (int bt = 0; bt < 2; bt++) {
                    mma16816(acc[mt][2 * bt],     af[mt], &bf[bt][0]);
                    mma16816(acc[mt][2 * bt + 1], af[mt], &bf[bt][2]);
                }
        }
    }

    // ---- epilogue: +bias (u only), fp16 pack, store ----
    #pragma unroll
    for (int mt = 0; mt < 2; mt++) {
        const int m0 = mbase + mt * 16 + (lane >> 2);
        #pragma unroll
        for (int half = 0; half < 2; half++) {
            const int grow = bm + m0 + half * 8;
            if (grow >= M) continue;
            unsigned short* orow = C + (size_t)grow * HIDDEN + nh;
            #pragma unroll
            for (int nt = 0; nt < 4; nt++) {
                const int n = nbase + nt * 8 + (lane & 3) * 2;
                float f0 = acc[mt][nt][2 * half];
                float f1 = acc[mt][nt][2 * half + 1];
                if (is_u) { f0 += sB1[n]; f1 += sB1[n + 1]; }
                __half2 h2 = __floats2half2_rn(f0, f1);
                *reinterpret_cast<__half2*>(orow + n) = h2;
            }
        }
    }
}

// ---------------------------------------------------------------------------
// Edge pass (fp16 tables): one warp per 2 edges (ILP for L2 latency hiding).
// ---------------------------------------------------------------------------
__global__ __launch_bounds__(256)
void edge_score_kernel(const int* __restrict__ src,
                       const int* __restrict__ dst,
                       const float* __restrict__ W2,
                       const float* __restrict__ b2,
                       float* __restrict__ out,
                       int E)
{
    __shared__ float sW2[HIDDEN];
    const int tid = threadIdx.x;
    sW2[tid] = W2[tid];
    __syncthreads();

    const int lane = tid & 31;
    const int warp = tid >> 5;

    const float4 wA = *reinterpret_cast<const float4*>(&sW2[lane * 8]);
    const float4 wB = *reinterpret_cast<const float4*>(&sW2[lane * 8 + 4]);
    const float w[8] = {wA.x, wA.y, wA.z, wA.w, wB.x, wB.y, wB.z, wB.w};
    const float bias = b2[0];

    const int e0 = (blockIdx.x * 8 + warp) * 2;
    if (e0 >= E) return;
    const bool has1 = (e0 + 1) < E;

    const int s0 = src[e0];
    const int d0 = dst[e0];
    const int s1 = has1 ? src[e0 + 1] : s0;
    const int d1 = has1 ? dst[e0 + 1] : d0;

    const uint4 u0 =
        reinterpret_cast<const uint4*>(g_u + (size_t)s0 * HIDDEN)[lane];
    const uint4 v0 =
        reinterpret_cast<const uint4*>(g_v + (size_t)d0 * HIDDEN)[lane];
    const uint4 u1 =
        reinterpret_cast<const uint4*>(g_u + (size_t)s1 * HIDDEN)[lane];
    const uint4 v1 =
        reinterpret_cast<const uint4*>(g_v + (size_t)d1 * HIDDEN)[lane];

    const __half2* u0h = reinterpret_cast<const __half2*>(&u0);
    const __half2* v0h = reinterpret_cast<const __half2*>(&v0);
    const __half2* u1h = reinterpret_cast<const __half2*>(&u1);
    const __half2* v1h = reinterpret_cast<const __half2*>(&v1);

    float acc0 = 0.f, acc1 = 0.f;
    #pragma unroll
    for (int i = 0; i < 4; i++) {
        float2 a = __half22float2(u0h[i]);
        float2 b = __half22float2(v0h[i]);
        acc0 = fmaf(fmaxf(a.x + b.x, 0.f), w[2 * i], acc0);
        acc0 = fmaf(fmaxf(a.y + b.y, 0.f), w[2 * i + 1], acc0);
        float2 c = __half22float2(u1h[i]);
        float2 d = __half22float2(v1h[i]);
        acc1 = fmaf(fmaxf(c.x + d.x, 0.f), w[2 * i], acc1);
        acc1 = fmaf(fmaxf(c.y + d.y, 0.f), w[2 * i + 1], acc1);
    }
    #pragma unroll
    for (int o = 16; o > 0; o >>= 1) {
        acc0 += __shfl_xor_sync(0xFFFFFFFFu, acc0, o);
        acc1 += __shfl_xor_sync(0xFFFFFFFFu, acc1, o);
    }

    if (lane == 0) {
        out[e0] = acc0 + bias;
        if (has1) out[e0 + 1] = acc1 + bias;
    }
}

// ---------------------------------------------------------------------------
extern "C" void kernel_launch(void* const* d_in, const int* in_sizes, int n_in,
                              void* d_out, int out_size)
{
    const float* Hs = (const float*)d_in[0];
    const float* Hd = (const float*)d_in[1];
    const int*   src = (const int*)d_in[2];
    const int*   dst = (const int*)d_in[3];
    const float* W1 = (const float*)d_in[4];
    const float* b1 = (const float*)d_in[5];
    const float* W2 = (const float*)d_in[6];
    const float* b2 = (const float*)d_in[7];
    float* out = (float*)d_out;

    const int M = in_sizes[0] / IN_FEATS;
    const int E = in_sizes[2];

    cudaFuncSetAttribute(node_gemm_mma,
                         cudaFuncAttributeMaxDynamicSharedMemorySize, SM_TOTAL);

    dim3 ggrid(2, (M + 63) / 64, 2);
    node_gemm_mma<<<ggrid, 256, SM_TOTAL>>>(Hs, Hd, W1, b1, M);

    edge_score_kernel<<<(E + 15) / 16, 256>>>(src, dst, W2, b2, out, E);
}

// round 5
// speedup vs baseline: 2.3922x; 2.3922x over previous
#include <cuda_runtime.h>
#include <cuda_fp16.h>
#include <cuda_bf16.h>
#include <cstdint>

#define IN_FEATS 128
#define HIDDEN   256
#define NMAX     100000
#define MPAD     (NMAX + 64)

// fp16 per-node projections: u = Hs@W1a + b1, v = Hd@W1b
__device__ __align__(16) unsigned short g_u[(size_t)NMAX * HIDDEN];
__device__ __align__(16) unsigned short g_v[(size_t)NMAX * HIDDEN];

// Pre-swizzled bf16 hi/lo images (SMEM-image layout, cp.async-ready).
// A images: [row][16 x 16B chunks], chunk c stored at c ^ (row & 7).
__device__ uint4 g_sAh[(size_t)MPAD * 16];
__device__ uint4 g_sAl[(size_t)MPAD * 16];
__device__ uint4 g_dAh[(size_t)MPAD * 16];
__device__ uint4 g_dAl[(size_t)MPAD * 16];
// W1 images: [isv][n(256)][16 chunks]  (B[n][k] = W1[isv*128 + k][n])
__device__ uint4 g_Wh[2 * 256 * 16];
__device__ uint4 g_Wl[2 * 256 * 16];

// ---------------------------------------------------------------------------
// helpers
// ---------------------------------------------------------------------------
__device__ __forceinline__ uint32_t smem_u32(const void* p) {
    uint32_t a;
    asm("{ .reg .u64 t; cvta.to.shared.u64 t, %1; cvt.u32.u64 %0, t; }"
        : "=r"(a) : "l"(p));
    return a;
}
__device__ __forceinline__ void cp_async16(uint32_t dst, const void* src) {
    asm volatile("cp.async.cg.shared.global [%0], [%1], 16;"
                 :: "r"(dst), "l"(src));
}
__device__ __forceinline__ void cp_async_wait_all() {
    asm volatile("cp.async.commit_group;");
    asm volatile("cp.async.wait_group 0;" ::: "memory");
}
__device__ __forceinline__ void ldsm4(uint32_t* r, uint32_t a) {
    asm volatile("ldmatrix.sync.aligned.m8n8.x4.shared.b16 {%0,%1,%2,%3}, [%4];"
                 : "=r"(r[0]), "=r"(r[1]), "=r"(r[2]), "=r"(r[3]) : "r"(a));
}
__device__ __forceinline__ void mma16816(float* d, const uint32_t* a,
                                         const uint32_t* b) {
    asm volatile(
        "mma.sync.aligned.m16n8k16.row.col.f32.bf16.bf16.f32 "
        "{%0,%1,%2,%3}, {%4,%5,%6,%7}, {%8,%9}, {%0,%1,%2,%3};"
        : "+f"(d[0]), "+f"(d[1]), "+f"(d[2]), "+f"(d[3])
        : "r"(a[0]), "r"(a[1]), "r"(a[2]), "r"(a[3]), "r"(b[0]), "r"(b[1]));
}

__device__ __forceinline__ uint32_t pack_bf2(__nv_bfloat16 a, __nv_bfloat16 b) {
    __nv_bfloat162 p(a, b);
    return *reinterpret_cast<uint32_t*>(&p);
}

// ---------------------------------------------------------------------------
// prep_A: fp32 H rows -> bf16 hi/lo swizzled images. One thread per 16B chunk.
// ---------------------------------------------------------------------------
__global__ __launch_bounds__(256)
void prep_A(const float* __restrict__ Hs, const float* __restrict__ Hd,
            int M, int Mpad)
{
    const int idx = blockIdx.x * 256 + threadIdx.x;
    if (idx >= Mpad * 16) return;
    const int n = idx >> 4;
    const int c = idx & 15;

    const float* __restrict__ H = blockIdx.y ? Hd : Hs;
    uint4* __restrict__ Ah = blockIdx.y ? g_dAh : g_sAh;
    uint4* __restrict__ Al = blockIdx.y ? g_dAl : g_sAl;

    uint4 hv = make_uint4(0, 0, 0, 0), lv = make_uint4(0, 0, 0, 0);
    if (n < M) {
        const float* p = H + (size_t)n * IN_FEATS + c * 8;
        const float4 x0 = *reinterpret_cast<const float4*>(p);
        const float4 x1 = *reinterpret_cast<const float4*>(p + 4);
        const float f[8] = {x0.x, x0.y, x0.z, x0.w, x1.x, x1.y, x1.z, x1.w};
        __nv_bfloat16 h[8], l[8];
        #pragma unroll
        for (int j = 0; j < 8; j++) {
            h[j] = __float2bfloat16(f[j]);
            l[j] = __float2bfloat16(f[j] - __bfloat162float(h[j]));
        }
        hv = make_uint4(pack_bf2(h[0], h[1]), pack_bf2(h[2], h[3]),
                        pack_bf2(h[4], h[5]), pack_bf2(h[6], h[7]));
        lv = make_uint4(pack_bf2(l[0], l[1]), pack_bf2(l[2], l[3]),
                        pack_bf2(l[4], l[5]), pack_bf2(l[6], l[7]));
    }
    const int dst = n * 16 + (c ^ (n & 7));
    Ah[dst] = hv;
    Al[dst] = lv;
}

// ---------------------------------------------------------------------------
// prep_W: W1 -> bf16 hi/lo swizzled B images. 8192 threads total.
// ---------------------------------------------------------------------------
__global__ __launch_bounds__(256)
void prep_W(const float* __restrict__ W1)
{
    const int idx = blockIdx.x * 256 + threadIdx.x;
    if (idx >= 2 * 256 * 16) return;
    const int isv = idx >> 12;
    const int n   = (idx >> 4) & 255;
    const int c   = idx & 15;

    __nv_bfloat16 h[8], l[8];
    #pragma unroll
    for (int j = 0; j < 8; j++) {
        const float w = W1[(size_t)(isv * 128 + c * 8 + j) * HIDDEN + n];
        h[j] = __float2bfloat16(w);
        l[j] = __float2bfloat16(w - __bfloat162float(h[j]));
    }
    const int dst = (isv * 256 + n) * 16 + (c ^ (n & 7));
    g_Wh[dst] = make_uint4(pack_bf2(h[0], h[1]), pack_bf2(h[2], h[3]),
                           pack_bf2(h[4], h[5]), pack_bf2(h[6], h[7]));
    g_Wl[dst] = make_uint4(pack_bf2(l[0], l[1]), pack_bf2(l[2], l[3]),
                           pack_bf2(l[4], l[5]), pack_bf2(l[6], l[7]));
}

// SMEM layout (dynamic): Ah | Al | Bh | Bl  (96KB -> 2 CTAs/SM)
static constexpr int SM_AH = 0;           // 64 rows x 256B = 16KB
static constexpr int SM_AL = 16384;
static constexpr int SM_BH = 32768;       // 128 rows x 256B = 32KB
static constexpr int SM_BL = 65536;
static constexpr int SM_TOTAL = 98304;

// ---------------------------------------------------------------------------
// Node GEMM: C-tile[64,128] = A[64,128] @ B[128,128], bf16 3-term split.
// Fill = pure cp.async copy of precomputed images. Compute loop = r4 verbatim.
// grid = (2 N-halves, ceil(M/64), 2 {u,v})
// ---------------------------------------------------------------------------
__global__ __launch_bounds__(256, 2)
void node_gemm_mma(const float* __restrict__ b1, int M)
{
    extern __shared__ char smem[];
    __shared__ float sB1[128];
    const uint32_t smb = smem_u32(smem);

    const int tid  = threadIdx.x;
    const int wid  = tid >> 5;
    const int lane = tid & 31;

    const bool is_u = (blockIdx.z == 0);
    unsigned short* __restrict__ C = is_u ? g_u : g_v;
    const int bm = blockIdx.y * 64;
    const int nh = blockIdx.x * 128;

    if (tid < 128) sB1[tid] = b1[nh + tid];

    // ---- fill via cp.async: A 2x16KB, B 2x32KB ----
    {
        const uint4* srcAh = (is_u ? g_sAh : g_dAh) + (size_t)bm * 16;
        const uint4* srcAl = (is_u ? g_sAl : g_dAl) + (size_t)bm * 16;
        const uint4* srcBh = g_Wh + ((is_u ? 0 : 256) + nh) * 16;
        const uint4* srcBl = g_Wl + ((is_u ? 0 : 256) + nh) * 16;
        #pragma unroll
        for (int i = 0; i < 4; i++) {
            const int o = tid + i * 256;
            cp_async16(smb + SM_AH + o * 16, srcAh + o);
            cp_async16(smb + SM_AL + o * 16, srcAl + o);
        }
        #pragma unroll
        for (int i = 0; i < 8; i++) {
            const int o = tid + i * 256;
            cp_async16(smb + SM_BH + o * 16, srcBh + o);
            cp_async16(smb + SM_BL + o * 16, srcBl + o);
        }
        cp_async_wait_all();
    }
    __syncthreads();

    // ---- compute: warp tile 32(M) x 32(N) ----
    const int mbase = (wid >> 2) * 32;
    const int nbase = (wid & 3) * 32;

    float acc[2][4][4];
    #pragma unroll
    for (int mt = 0; mt < 2; mt++)
        #pragma unroll
        for (int nt = 0; nt < 4; nt++)
            #pragma unroll
            for (int q = 0; q < 4; q++) acc[mt][nt][q] = 0.f;

    const uint32_t rowA  = (uint32_t)(mbase + (lane & 15));
    const uint32_t xorA  = rowA & 7u;
    const uint32_t chA0  = (uint32_t)(lane >> 4);
    const uint32_t baseA = rowA * 256u;

    const uint32_t rowB  = (uint32_t)(nbase + (lane & 7) + ((lane >> 4) << 3));
    const uint32_t xorB  = rowB & 7u;
    const uint32_t chB0  = (uint32_t)((lane >> 3) & 1);
    const uint32_t baseB = rowB * 256u;

    #pragma unroll
    for (int term = 0; term < 3; term++) {
        const uint32_t aBase = smb + (term == 2 ? SM_AL : SM_AH);
        const uint32_t bBase = smb + (term == 1 ? SM_BL : SM_BH);
        #pragma unroll
        for (int ks = 0; ks < 8; ks++) {
            const uint32_t aAddr0 =
                aBase + baseA + (((chA0 + 2u * ks) ^ xorA) << 4);
            const uint32_t bAddr0 =
                bBase + baseB + (((chB0 + 2u * ks) ^ xorB) << 4);
            uint32_t af[2][4], bf[2][4];
            #pragma unroll
            for (int mt = 0; mt < 2; mt++)
                ldsm4(af[mt], aAddr0 + mt * 16 * 256);
            #pragma unroll
            for (int bt = 0; bt < 2; bt++)
                ldsm4(bf[bt], bAddr0 + bt * 16 * 256);
            #pragma unroll
            for (int mt = 0; mt < 2; mt++)
                #pragma unroll
                for (int bt = 0; bt < 2; bt++) {
                    mma16816(acc[mt][2 * bt],     af[mt], &bf[bt][0]);
                    mma16816(acc[mt][2 * bt + 1], af[mt], &bf[bt][2]);
                }
        }
    }

    // ---- epilogue: +bias (u only), fp16 pack, store ----
    #pragma unroll
    for (int mt = 0; mt < 2; mt++) {
        const int m0 = mbase + mt * 16 + (lane >> 2);
        #pragma unroll
        for (int half = 0; half < 2; half++) {
            const int grow = bm + m0 + half * 8;
            if (grow >= M) continue;
            unsigned short* orow = C + (size_t)grow * HIDDEN + nh;
            #pragma unroll
            for (int nt = 0; nt < 4; nt++) {
                const int n = nbase + nt * 8 + (lane & 3) * 2;
                float f0 = acc[mt][nt][2 * half];
                float f1 = acc[mt][nt][2 * half + 1];
                if (is_u) { f0 += sB1[n]; f1 += sB1[n + 1]; }
                __half2 h2 = __floats2half2_rn(f0, f1);
                *reinterpret_cast<__half2*>(orow + n) = h2;
            }
        }
    }
}

// ---------------------------------------------------------------------------
// Edge pass (fp16 tables): 4 edges per warp for L2-latency-hiding ILP.
// ---------------------------------------------------------------------------
__global__ __launch_bounds__(256)
void edge_score_kernel(const int* __restrict__ src,
                       const int* __restrict__ dst,
                       const float* __restrict__ W2,
                       const float* __restrict__ b2,
                       float* __restrict__ out,
                       int E)
{
    __shared__ float sW2[HIDDEN];
    const int tid = threadIdx.x;
    sW2[tid] = W2[tid];
    __syncthreads();

    const int lane = tid & 31;
    const int warp = tid >> 5;

    const float4 wA = *reinterpret_cast<const float4*>(&sW2[lane * 8]);
    const float4 wB = *reinterpret_cast<const float4*>(&sW2[lane * 8 + 4]);
    const float w[8] = {wA.x, wA.y, wA.z, wA.w, wB.x, wB.y, wB.z, wB.w};
    const float bias = b2[0];

    const int e0 = (blockIdx.x * 8 + warp) * 4;
    if (e0 >= E) return;

    int si[4], di[4];
    #pragma unroll
    for (int j = 0; j < 4; j++) {
        const int e = min(e0 + j, E - 1);
        si[j] = src[e];
        di[j] = dst[e];
    }

    uint4 ur[4], vr[4];
    #pragma unroll
    for (int j = 0; j < 4; j++) {
        ur[j] = reinterpret_cast<const uint4*>(g_u + (size_t)si[j] * HIDDEN)[lane];
        vr[j] = reinterpret_cast<const uint4*>(g_v + (size_t)di[j] * HIDDEN)[lane];
    }

    float acc[4] = {0.f, 0.f, 0.f, 0.f};
    #pragma unroll
    for (int j = 0; j < 4; j++) {
        const __half2* uh = reinterpret_cast<const __half2*>(&ur[j]);
        const __half2* vh = reinterpret_cast<const __half2*>(&vr[j]);
        #pragma unroll
        for (int i = 0; i < 4; i++) {
            float2 a = __half22float2(uh[i]);
            float2 b = __half22float2(vh[i]);
            acc[j] = fmaf(fmaxf(a.x + b.x, 0.f), w[2 * i], acc[j]);
            acc[j] = fmaf(fmaxf(a.y + b.y, 0.f), w[2 * i + 1], acc[j]);
        }
    }
    #pragma unroll
    for (int o = 16; o > 0; o >>= 1) {
        #pragma unroll
        for (int j = 0; j < 4; j++)
            acc[j] += __shfl_xor_sync(0xFFFFFFFFu, acc[j], o);
    }

    if (lane == 0) {
        #pragma unroll
        for (int j = 0; j < 4; j++)
            if (e0 + j < E) out[e0 + j] = acc[j] + bias;
    }
}

// ---------------------------------------------------------------------------
extern "C" void kernel_launch(void* const* d_in, const int* in_sizes, int n_in,
                              void* d_out, int out_size)
{
    const float* Hs = (const float*)d_in[0];
    const float* Hd = (const float*)d_in[1];
    const int*   src = (const int*)d_in[2];
    const int*   dst = (const int*)d_in[3];
    const float* W1 = (const float*)d_in[4];
    const float* b1 = (const float*)d_in[5];
    const float* W2 = (const float*)d_in[6];
    const float* b2 = (const float*)d_in[7];
    float* out = (float*)d_out;

    const int M = in_sizes[0] / IN_FEATS;
    const int E = in_sizes[2];
    const int Mpad = ((M + 63) / 64) * 64;

    cudaFuncSetAttribute(node_gemm_mma,
                         cudaFuncAttributeMaxDynamicSharedMemorySize, SM_TOTAL);

    dim3 pa_grid((Mpad * 16 + 255) / 256, 2);
    prep_A<<<pa_grid, 256>>>(Hs, Hd, M, Mpad);
    prep_W<<<32, 256>>>(W1);

    dim3 ggrid(2, (M + 63) / 64, 2);
    node_gemm_mma<<<ggrid, 256, SM_TOTAL>>>(b1, M);

    edge_score_kernel<<<(E + 31) / 32, 256>>>(src, dst, W2, b2, out, E);
}

// round 7
// speedup vs baseline: 2.5221x; 1.0543x over previous
#include <cuda_runtime.h>
#include <cuda_fp16.h>
#include <cuda_bf16.h>
#include <cstdint>

#define IN_FEATS 128
#define HIDDEN   256
#define NMAX     100000

// fp16 per-node projections: u = Hs@W1a + b1, v = Hd@W1b
__device__ __align__(16) unsigned short g_u[(size_t)NMAX * HIDDEN];
__device__ __align__(16) unsigned short g_v[(size_t)NMAX * HIDDEN];

// W1 bf16 hi/lo swizzled images: [isv][n(256)][16 chunks]
__device__ uint4 g_Wh[2 * 256 * 16];
__device__ uint4 g_Wl[2 * 256 * 16];

// ---------------------------------------------------------------------------
// helpers
// ---------------------------------------------------------------------------
__device__ __forceinline__ uint32_t smem_u32(const void* p) {
    uint32_t a;
    asm("{ .reg .u64 t; cvta.to.shared.u64 t, %1; cvt.u32.u64 %0, t; }"
        : "=r"(a) : "l"(p));
    return a;
}
__device__ __forceinline__ void cp_async16(uint32_t dst, const void* src) {
    asm volatile("cp.async.cg.shared.global [%0], [%1], 16;"
                 :: "r"(dst), "l"(src));
}
__device__ __forceinline__ void cp_async16z(uint32_t dst, const void* src,
                                            int srcsz) {
    asm volatile("cp.async.cg.shared.global [%0], [%1], 16, %2;"
                 :: "r"(dst), "l"(src), "r"(srcsz));
}
__device__ __forceinline__ void cp_async_commit() {
    asm volatile("cp.async.commit_group;");
}
__device__ __forceinline__ void cp_async_wait_all() {
    asm volatile("cp.async.wait_group 0;" ::: "memory");
}
__device__ __forceinline__ void ldsm4(uint32_t* r, uint32_t a) {
    asm volatile("ldmatrix.sync.aligned.m8n8.x4.shared.b16 {%0,%1,%2,%3}, [%4];"
                 : "=r"(r[0]), "=r"(r[1]), "=r"(r[2]), "=r"(r[3]) : "r"(a));
}
__device__ __forceinline__ void mma16816(float* d, const uint32_t* a,
                                         const uint32_t* b) {
    asm volatile(
        "mma.sync.aligned.m16n8k16.row.col.f32.bf16.bf16.f32 "
        "{%0,%1,%2,%3}, {%4,%5,%6,%7}, {%8,%9}, {%0,%1,%2,%3};"
        : "+f"(d[0]), "+f"(d[1]), "+f"(d[2]), "+f"(d[3])
        : "r"(a[0]), "r"(a[1]), "r"(a[2]), "r"(a[3]), "r"(b[0]), "r"(b[1]));
}
__device__ __forceinline__ uint32_t pack_bf2(__nv_bfloat16 a, __nv_bfloat16 b) {
    __nv_bfloat162 p(a, b);
    return *reinterpret_cast<uint32_t*>(&p);
}
// row-local XOR swizzle for bf16 tiles: rows 256B, chunk(16B) ^= (row & 7)
__device__ __forceinline__ uint32_t swz(uint32_t row, uint32_t kbyte) {
    return row * 256u + ((((kbyte >> 4) ^ (row & 7u)) << 4) | (kbyte & 15u));
}

// ---------------------------------------------------------------------------
// prep_W: W1 -> bf16 hi/lo swizzled B images (one-time, 256KB, L2-resident).
// ---------------------------------------------------------------------------
__global__ __launch_bounds__(256)
void prep_W(const float* __restrict__ W1)
{
    const int idx = blockIdx.x * 256 + threadIdx.x;
    if (idx >= 2 * 256 * 16) return;
    const int isv = idx >> 12;
    const int n   = (idx >> 4) & 255;
    const int c   = idx & 15;

    __nv_bfloat16 h[8], l[8];
    #pragma unroll
    for (int j = 0; j < 8; j++) {
        const float w = W1[(size_t)(isv * 128 + c * 8 + j) * HIDDEN + n];
        h[j] = __float2bfloat16(w);
        l[j] = __float2bfloat16(w - __bfloat162float(h[j]));
    }
    const int dst = (isv * 256 + n) * 16 + (c ^ (n & 7));
    g_Wh[dst] = make_uint4(pack_bf2(h[0], h[1]), pack_bf2(h[2], h[3]),
                           pack_bf2(h[4], h[5]), pack_bf2(h[6], h[7]));
    g_Wl[dst] = make_uint4(pack_bf2(l[0], l[1]), pack_bf2(l[2], l[3]),
                           pack_bf2(l[4], l[5]), pack_bf2(l[6], l[7]));
}

// SMEM layout (dynamic):
static constexpr int SM_BH = 0;           // 256 rows x 256B = 64KB
static constexpr int SM_BL = 65536;       // 64KB
static constexpr int SM_AH = 131072;      // 64 rows x 256B = 16KB
static constexpr int SM_AL = 147456;      // 16KB
static constexpr int SM_AF = 163840;      // fp32 staging: 64 rows x 528B = 33792
static constexpr int AF_STRIDE = 528;     // 512B + 16B pad (bank spread)
static constexpr int SM_TOTAL = 197632;

// issue cp.async for fp32 A tile (64 rows x 128 f32), ZFILL beyond M
__device__ __forceinline__ void load_A_async(const float* __restrict__ A,
                                             int M, int bm, uint32_t smb,
                                             int tid)
{
    #pragma unroll
    for (int i = 0; i < 8; i++) {
        const int o   = tid + i * 256;     // chunk 0..2047
        const int row = o >> 5;            // 32 chunks per row
        const int c   = o & 31;
        const float* src = A + (size_t)(bm + row) * IN_FEATS + c * 4;
        const uint32_t dst = smb + SM_AF + row * AF_STRIDE + c * 16;
        cp_async16z(dst, src, (bm + row < M) ? 16 : 0);
    }
    cp_async_commit();
}

// ---------------------------------------------------------------------------
// Persistent node GEMM: one CTA per SM. B (full N=256 hi/lo) loaded once;
// loops over M-tiles of 64 with cp.async prefetch of fp32 A overlapped with
// MMA; in-SMEM convert to swizzled bf16 hi/lo. 3-term split, r5 math.
// blockIdx.x & 1 = {u, v}.
// ---------------------------------------------------------------------------
__global__ __launch_bounds__(256, 1)
void node_gemm_persistent(const float* __restrict__ Hs,
                          const float* __restrict__ Hd,
                          const float* __restrict__ b1,
                          int M, int nTiles)
{
    extern __shared__ char smem[];
    __shared__ float sB1[HIDDEN];
    const uint32_t smb = smem_u32(smem);

    const int tid  = threadIdx.x;
    const int wid  = tid >> 5;
    const int lane = tid & 31;

    const bool is_u = (blockIdx.x & 1) == 0;
    const int  cta  = blockIdx.x >> 1;
    const int  nCta = gridDim.x >> 1;
    const float* __restrict__ A = is_u ? Hs : Hd;
    unsigned short* __restrict__ C = is_u ? g_u : g_v;

    // ---- one-time: B images (128KB) + bias + first A tile ----
    {
        const uint4* srcBh = g_Wh + (is_u ? 0 : 4096);
        const uint4* srcBl = g_Wl + (is_u ? 0 : 4096);
        #pragma unroll
        for (int i = 0; i < 16; i++) {
            const int o = tid + i * 256;
            cp_async16(smb + SM_BH + o * 16, srcBh + o);
            cp_async16(smb + SM_BL + o * 16, srcBl + o);
        }
        cp_async_commit();
    }
    sB1[tid] = b1[tid];
    if (cta < nTiles) load_A_async(A, M, cta * 64, smb, tid);
    cp_async_wait_all();
    __syncthreads();

    // warp tiling: 2(M) x 4(N64) over 64x256
    const int mbase = (wid >> 2) * 32;
    const int nbase = (wid & 3) * 64;

    const uint32_t rowA  = (uint32_t)(mbase + (lane & 15));
    const uint32_t xorA  = rowA & 7u;
    const uint32_t chA0  = (uint32_t)(lane >> 4);
    const uint32_t baseA = rowA * 256u;

    const uint32_t rowB  = (uint32_t)(nbase + (lane & 7) + ((lane >> 4) << 3));
    const uint32_t xorB  = rowB & 7u;
    const uint32_t chB0  = (uint32_t)((lane >> 3) & 1);
    const uint32_t baseB = rowB * 256u;

    // convert-thread mapping: row tid/4, k-quarter (tid&3)*32
    const int cvRow = tid >> 2;
    const int cvKq  = (tid & 3) * 32;
    const char* cvStage = smem + SM_AF + cvRow * AF_STRIDE;

    for (int t = cta; t < nTiles; t += nCta) {
        const int bm = t * 64;

        // ---- convert fp32 staging -> swizzled bf16 hi/lo ----
        #pragma unroll
        for (int j = 0; j < 8; j++) {
            const int k = cvKq + j * 4;
            const float4 x = *reinterpret_cast<const float4*>(cvStage + k * 4);
            __nv_bfloat16 h0 = __float2bfloat16(x.x), h1 = __float2bfloat16(x.y);
            __nv_bfloat16 h2 = __float2bfloat16(x.z), h3 = __float2bfloat16(x.w);
            __nv_bfloat16 l0 = __float2bfloat16(x.x - __bfloat162float(h0));
            __nv_bfloat16 l1 = __float2bfloat16(x.y - __bfloat162float(h1));
            __nv_bfloat16 l2 = __float2bfloat16(x.z - __bfloat162float(h2));
            __nv_bfloat16 l3 = __float2bfloat16(x.w - __bfloat162float(h3));
            const uint32_t o = swz((uint32_t)cvRow, (uint32_t)(k * 2));
            uint2 hv, lv;
            hv.x = pack_bf2(h0, h1); hv.y = pack_bf2(h2, h3);
            lv.x = pack_bf2(l0, l1); lv.y = pack_bf2(l2, l3);
            *reinterpret_cast<uint2*>(smem + SM_AH + o) = hv;
            *reinterpret_cast<uint2*>(smem + SM_AL + o) = lv;
        }
        __syncthreads();

        // ---- prefetch next A tile (overlaps MMA below) ----
        const int tn = t + nCta;
        if (tn < nTiles) load_A_async(A, M, tn * 64, smb, tid);

        // ---- MMA: 3 terms x 8 ksteps, warp 32M x 64N ----
        float acc[2][8][4];
        #pragma unroll
        for (int mt = 0; mt < 2; mt++)
            #pragma unroll
            for (int nt = 0; nt < 8; nt++)
                #pragma unroll
                for (int q = 0; q < 4; q++) acc[mt][nt][q] = 0.f;

        #pragma unroll
        for (int term = 0; term < 3; term++) {
            const uint32_t aBase = smb + (term == 2 ? SM_AL : SM_AH);
            const uint32_t bBase = smb + (term == 1 ? SM_BL : SM_BH);
            #pragma unroll
            for (int ks = 0; ks < 8; ks++) {
                const uint32_t aAddr0 =
                    aBase + baseA + (((chA0 + 2u * ks) ^ xorA) << 4);
                const uint32_t bAddr0 =
                    bBase + baseB + (((chB0 + 2u * ks) ^ xorB) << 4);
                uint32_t af[2][4], bf[4][4];
                #pragma unroll
                for (int mt = 0; mt < 2; mt++)
                    ldsm4(af[mt], aAddr0 + mt * 16 * 256);
                #pragma unroll
                for (int bt = 0; bt < 4; bt++)
                    ldsm4(bf[bt], bAddr0 + bt * 16 * 256);
                #pragma unroll
                for (int mt = 0; mt < 2; mt++)
                    #pragma unroll
                    for (int bt = 0; bt < 4; bt++) {
                        mma16816(acc[mt][2 * bt],     af[mt], &bf[bt][0]);
                        mma16816(acc[mt][2 * bt + 1], af[mt], &bf[bt][2]);
                    }
            }
        }

        // ---- epilogue: +bias (u only), fp16 pack, store ----
        #pragma unroll
        for (int mt = 0; mt < 2; mt++) {
            const int m0 = mbase + mt * 16 + (lane >> 2);
            #pragma unroll
            for (int half = 0; half < 2; half++) {
                const int grow = bm + m0 + half * 8;
                if (grow >= M) continue;
                unsigned short* orow = C + (size_t)grow * HIDDEN;
                #pragma unroll
                for (int nt = 0; nt < 8; nt++) {
                    const int n = nbase + nt * 8 + (lane & 3) * 2;
                    float f0 = acc[mt][nt][2 * half];
                    float f1 = acc[mt][nt][2 * half + 1];
                    if (is_u) { f0 += sB1[n]; f1 += sB1[n + 1]; }
                    __half2 h2 = __floats2half2_rn(f0, f1);
                    *reinterpret_cast<__half2*>(orow + n) = h2;
                }
            }
        }

        cp_async_wait_all();    // next fp32 A tile landed
        __syncthreads();        // all epilogue/ldsm done before next convert
    }
}

// ---------------------------------------------------------------------------
// Edge pass (r4-verified, 110us): full warp per edge, 2 edges per warp.
// ---------------------------------------------------------------------------
__global__ __launch_bounds__(256)
void edge_score_kernel(const int* __restrict__ src,
                       const int* __restrict__ dst,
                       const float* __restrict__ W2,
                       const float* __restrict__ b2,
                       float* __restrict__ out,
                       int E)
{
    __shared__ float sW2[HIDDEN];
    const int tid = threadIdx.x;
    sW2[tid] = W2[tid];
    __syncthreads();

    const int lane = tid & 31;
    const int warp = tid >> 5;

    const float4 wA = *reinterpret_cast<const float4*>(&sW2[lane * 8]);
    const float4 wB = *reinterpret_cast<const float4*>(&sW2[lane * 8 + 4]);
    const float w[8] = {wA.x, wA.y, wA.z, wA.w, wB.x, wB.y, wB.z, wB.w};
    const float bias = b2[0];

    const int e0 = (blockIdx.x * 8 + warp) * 2;
    if (e0 >= E) return;
    const bool has1 = (e0 + 1) < E;

    const int s0 = src[e0];
    const int d0 = dst[e0];
    const int s1 = has1 ? src[e0 + 1] : s0;
    const int d1 = has1 ? dst[e0 + 1] : d0;

    const uint4 u0 =
        reinterpret_cast<const uint4*>(g_u + (size_t)s0 * HIDDEN)[lane];
    const uint4 v0 =
        reinterpret_cast<const uint4*>(g_v + (size_t)d0 * HIDDEN)[lane];
    const uint4 u1 =
        reinterpret_cast<const uint4*>(g_u + (size_t)s1 * HIDDEN)[lane];
    const uint4 v1 =
        reinterpret_cast<const uint4*>(g_v + (size_t)d1 * HIDDEN)[lane];

    const __half2* u0h = reinterpret_cast<const __half2*>(&u0);
    const __half2* v0h = reinterpret_cast<const __half2*>(&v0);
    const __half2* u1h = reinterpret_cast<const __half2*>(&u1);
    const __half2* v1h = reinterpret_cast<const __half2*>(&v1);

    float acc0 = 0.f, acc1 = 0.f;
    #pragma unroll
    for (int i = 0; i < 4; i++) {
        float2 a = __half22float2(u0h[i]);
        float2 b = __half22float2(v0h[i]);
        acc0 = fmaf(fmaxf(a.x + b.x, 0.f), w[2 * i], acc0);
        acc0 = fmaf(fmaxf(a.y + b.y, 0.f), w[2 * i + 1], acc0);
        float2 c = __half22float2(u1h[i]);
        float2 d = __half22float2(v1h[i]);
        acc1 = fmaf(fmaxf(c.x + d.x, 0.f), w[2 * i], acc1);
        acc1 = fmaf(fmaxf(c.y + d.y, 0.f), w[2 * i + 1], acc1);
    }
    #pragma unroll
    for (int o = 16; o > 0; o >>= 1) {
        acc0 += __shfl_xor_sync(0xFFFFFFFFu, acc0, o);
        acc1 += __shfl_xor_sync(0xFFFFFFFFu, acc1, o);
    }

    if (lane == 0) {
        out[e0] = acc0 + bias;
        if (has1) out[e0 + 1] = acc1 + bias;
    }
}

// ---------------------------------------------------------------------------
extern "C" void kernel_launch(void* const* d_in, const int* in_sizes, int n_in,
                              void* d_out, int out_size)
{
    const float* Hs = (const float*)d_in[0];
    const float* Hd = (const float*)d_in[1];
    const int*   src = (const int*)d_in[2];
    const int*   dst = (const int*)d_in[3];
    const float* W1 = (const float*)d_in[4];
    const float* b1 = (const float*)d_in[5];
    const float* W2 = (const float*)d_in[6];
    const float* b2 = (const float*)d_in[7];
    float* out = (float*)d_out;

    const int M = in_sizes[0] / IN_FEATS;
    const int E = in_sizes[2];
    const int nTiles = (M + 63) / 64;

    cudaFuncSetAttribute(node_gemm_persistent,
                         cudaFuncAttributeMaxDynamicSharedMemorySize, SM_TOTAL);

    prep_W<<<32, 256>>>(W1);
    node_gemm_persistent<<<148, 256, SM_TOTAL>>>(Hs, Hd, b1, M, nTiles);
    edge_score_kernel<<<(E + 15) / 16, 256>>>(src, dst, W2, b2, out, E);
}

// round 8
// speedup vs baseline: 3.2169x; 1.2755x over previous
#include <cuda_runtime.h>
#include <cuda_fp16.h>
#include <cuda_bf16.h>
#include <cstdint>

#define IN_FEATS 128
#define HIDDEN   256
#define NMAX     100000

// fp16 per-node projections: u = Hs@W1a + b1, v = Hd@W1b
__device__ __align__(16) unsigned short g_u[(size_t)NMAX * HIDDEN];
__device__ __align__(16) unsigned short g_v[(size_t)NMAX * HIDDEN];

// W1 as tf32 fragment-major images: [isv(2)][ntile(32)][kstep(16)][lane(32)]{b0,b1}
__device__ uint2 g_Wf[2 * 32 * 16 * 32];

// ---------------------------------------------------------------------------
// helpers
// ---------------------------------------------------------------------------
__device__ __forceinline__ uint32_t smem_u32(const void* p) {
    uint32_t a;
    asm("{ .reg .u64 t; cvta.to.shared.u64 t, %1; cvt.u32.u64 %0, t; }"
        : "=r"(a) : "l"(p));
    return a;
}
__device__ __forceinline__ void cp_async16(uint32_t dst, const void* src) {
    asm volatile("cp.async.cg.shared.global [%0], [%1], 16;"
                 :: "r"(dst), "l"(src));
}
__device__ __forceinline__ void cp_async16z(uint32_t dst, const void* src,
                                            int srcsz) {
    asm volatile("cp.async.cg.shared.global [%0], [%1], 16, %2;"
                 :: "r"(dst), "l"(src), "r"(srcsz));
}
__device__ __forceinline__ void cp_async_commit() {
    asm volatile("cp.async.commit_group;");
}
__device__ __forceinline__ void cp_async_wait_all() {
    asm volatile("cp.async.wait_group 0;" ::: "memory");
}
__device__ __forceinline__ uint32_t f2tf32(float f) {
    uint32_t r;
    asm("cvt.rna.tf32.f32 %0, %1;" : "=r"(r) : "f"(f));
    return r;
}
// m16n8k8 tf32 mma, fp32 accum
__device__ __forceinline__ void mma_tf32(float* d, const uint32_t* a,
                                         const uint32_t* b) {
    asm volatile(
        "mma.sync.aligned.m16n8k8.row.col.f32.tf32.tf32.f32 "
        "{%0,%1,%2,%3}, {%4,%5,%6,%7}, {%8,%9}, {%0,%1,%2,%3};"
        : "+f"(d[0]), "+f"(d[1]), "+f"(d[2]), "+f"(d[3])
        : "r"(a[0]), "r"(a[1]), "r"(a[2]), "r"(a[3]), "r"(b[0]), "r"(b[1]));
}

// ---------------------------------------------------------------------------
// prep_W: W1 -> tf32 fragment-major B images (one-time, 256KB, L2-resident).
// B fragment (col-major B, K x N = 8x8): b0 = B[k=lane%4][n=lane/4],
// b1 = B[k=lane%4+4][n=lane/4]; B[k][n] = W1[isv*128 + k][n].
// ---------------------------------------------------------------------------
__global__ __launch_bounds__(256)
void prep_W(const float* __restrict__ W1)
{
    const int idx = blockIdx.x * 256 + threadIdx.x;
    if (idx >= 2 * 32 * 16 * 32) return;
    const int isv  = idx >> 14;
    const int nt   = (idx >> 9) & 31;
    const int ks   = (idx >> 5) & 15;
    const int lane = idx & 31;

    const int n = nt * 8 + (lane >> 2);
    const int k = ks * 8 + (lane & 3);
    const float w0 = W1[(size_t)(isv * 128 + k) * HIDDEN + n];
    const float w1 = W1[(size_t)(isv * 128 + k + 4) * HIDDEN + n];
    g_Wf[idx] = make_uint2(f2tf32(w0), f2tf32(w1));
}

// SMEM layout (dynamic):
static constexpr int SM_B  = 0;           // B frags: 32*16*32*8  = 128KB
static constexpr int SM_A  = 131072;      // A frags: 4*16*32*16  = 32KB
static constexpr int SM_AF = 163840;      // fp32 staging 64 x 528B
static constexpr int AF_STRIDE = 528;     // 132 floats; 132 % 32 = 4 -> no conflicts
static constexpr int SM_TOTAL = 197632;

// issue cp.async for fp32 A tile (64 rows x 128 f32), ZFILL beyond M
__device__ __forceinline__ void load_A_async(const float* __restrict__ A,
                                             int M, int bm, uint32_t smb,
                                             int tid)
{
    #pragma unroll
    for (int i = 0; i < 8; i++) {
        const int o   = tid + i * 256;
        const int row = o >> 5;
        const int c   = o & 31;
        const float* src = A + (size_t)(bm + row) * IN_FEATS + c * 4;
        const uint32_t dst = smb + SM_AF + row * AF_STRIDE + c * 16;
        cp_async16z(dst, src, (bm + row < M) ? 16 : 0);
    }
    cp_async_commit();
}

// ---------------------------------------------------------------------------
// Persistent node GEMM (tf32 single pass): one CTA per SM; B loaded once;
// per 64-row M tile: cp.async fp32 A (prefetched), convert to fragment-major
// tf32 in SMEM, 16 ksteps of m16n8k8. blockIdx.x & 1 = {u, v}.
// ---------------------------------------------------------------------------
__global__ __launch_bounds__(256, 1)
void node_gemm_persistent(const float* __restrict__ Hs,
                          const float* __restrict__ Hd,
                          const float* __restrict__ b1,
                          int M, int nTiles)
{
    extern __shared__ char smem[];
    __shared__ float sB1[HIDDEN];
    const uint32_t smb = smem_u32(smem);

    const int tid  = threadIdx.x;
    const int wid  = tid >> 5;
    const int lane = tid & 31;

    const bool is_u = (blockIdx.x & 1) == 0;
    const int  cta  = blockIdx.x >> 1;
    const int  nCta = gridDim.x >> 1;
    const float* __restrict__ A = is_u ? Hs : Hd;
    unsigned short* __restrict__ C = is_u ? g_u : g_v;

    // ---- one-time: B fragments (128KB) + bias + first A tile ----
    {
        const uint2* srcB = g_Wf + (is_u ? 0 : 16384);
        #pragma unroll
        for (int i = 0; i < 32; i++) {
            const int o = tid + i * 256;          // 16B granules
            cp_async16(smb + SM_B + o * 16, reinterpret_cast<const char*>(srcB) + o * 16);
        }
        cp_async_commit();
    }
    sB1[tid] = b1[tid];
    if (cta < nTiles) load_A_async(A, M, cta * 64, smb, tid);
    cp_async_wait_all();
    __syncthreads();

    // warp tiling: 2(M) x 4(N64) over 64x256
    const int mtb = (wid >> 2) * 2;        // first m16 tile index (of 4)
    const int ntb = (wid & 3) * 8;         // first n8 tile index (of 32)
    const int mbase = mtb * 16;
    const int nbase = ntb * 8;

    for (int t = cta; t < nTiles; t += nCta) {
        const int bm = t * 64;

        // ---- convert fp32 staging -> fragment-major tf32 A ----
        // slot = ((mt*16 + ks)*32 + lane); 8 slots per thread.
        #pragma unroll
        for (int i = 0; i < 8; i++) {
            const int slot = tid + i * 256;
            const int mt = slot >> 9;
            const int ks = (slot >> 5) & 15;
            const int ln = slot & 31;
            const int r = mt * 16 + (ln >> 2);
            const int k = ks * 8 + (ln & 3);
            const float* st = reinterpret_cast<const float*>(
                smem + SM_AF + r * AF_STRIDE);
            const float* st8 = reinterpret_cast<const float*>(
                smem + SM_AF + (r + 8) * AF_STRIDE);
            uint4 frag;
            frag.x = f2tf32(st[k]);
            frag.y = f2tf32(st8[k]);
            frag.z = f2tf32(st[k + 4]);
            frag.w = f2tf32(st8[k + 4]);
            *reinterpret_cast<uint4*>(smem + SM_A + slot * 16) = frag;
        }
        __syncthreads();

        // ---- prefetch next A tile (overlaps MMA below) ----
        const int tn = t + nCta;
        if (tn < nTiles) load_A_async(A, M, tn * 64, smb, tid);

        // ---- MMA: 16 ksteps, warp 32M x 64N ----
        float acc[2][8][4];
        #pragma unroll
        for (int mt = 0; mt < 2; mt++)
            #pragma unroll
            for (int nt = 0; nt < 8; nt++)
                #pragma unroll
                for (int q = 0; q < 4; q++) acc[mt][nt][q] = 0.f;

        #pragma unroll
        for (int ks = 0; ks < 16; ks++) {
            uint4 a[2];
            #pragma unroll
            for (int mt = 0; mt < 2; mt++)
                a[mt] = *reinterpret_cast<const uint4*>(
                    smem + SM_A + (((mtb + mt) * 16 + ks) * 32 + lane) * 16);
            #pragma unroll
            for (int nt = 0; nt < 8; nt++) {
                const uint2 b = *reinterpret_cast<const uint2*>(
                    smem + SM_B + (((ntb + nt) * 16 + ks) * 32 + lane) * 8);
                const uint32_t br[2] = {b.x, b.y};
                mma_tf32(acc[0][nt], reinterpret_cast<const uint32_t*>(&a[0]), br);
                mma_tf32(acc[1][nt], reinterpret_cast<const uint32_t*>(&a[1]), br);
            }
        }

        // ---- epilogue: +bias (u only), fp16 pack, store ----
        #pragma unroll
        for (int mt = 0; mt < 2; mt++) {
            const int m0 = mbase + mt * 16 + (lane >> 2);
            #pragma unroll
            for (int half = 0; half < 2; half++) {
                const int grow = bm + m0 + half * 8;
                if (grow >= M) continue;
                unsigned short* orow = C + (size_t)grow * HIDDEN;
                #pragma unroll
                for (int nt = 0; nt < 8; nt++) {
                    const int n = nbase + nt * 8 + (lane & 3) * 2;
                    float f0 = acc[mt][nt][2 * half];
                    float f1 = acc[mt][nt][2 * half + 1];
                    if (is_u) { f0 += sB1[n]; f1 += sB1[n + 1]; }
                    __half2 h2 = __floats2half2_rn(f0, f1);
                    *reinterpret_cast<__half2*>(orow + n) = h2;
                }
            }
        }

        cp_async_wait_all();    // next fp32 A tile landed
        __syncthreads();        // epilogue/frag reads done before next convert
    }
}

// ---------------------------------------------------------------------------
// Edge pass (r4-verified): full warp per edge, 2 edges per warp.
// ---------------------------------------------------------------------------
__global__ __launch_bounds__(256)
void edge_score_kernel(const int* __restrict__ src,
                       const int* __restrict__ dst,
                       const float* __restrict__ W2,
                       const float* __restrict__ b2,
                       float* __restrict__ out,
                       int E)
{
    __shared__ float sW2[HIDDEN];
    const int tid = threadIdx.x;
    sW2[tid] = W2[tid];
    __syncthreads();

    const int lane = tid & 31;
    const int warp = tid >> 5;

    const float4 wA = *reinterpret_cast<const float4*>(&sW2[lane * 8]);
    const float4 wB = *reinterpret_cast<const float4*>(&sW2[lane * 8 + 4]);
    const float w[8] = {wA.x, wA.y, wA.z, wA.w, wB.x, wB.y, wB.z, wB.w};
    const float bias = b2[0];

    const int e0 = (blockIdx.x * 8 + warp) * 2;
    if (e0 >= E) return;
    const bool has1 = (e0 + 1) < E;

    const int s0 = src[e0];
    const int d0 = dst[e0];
    const int s1 = has1 ? src[e0 + 1] : s0;
    const int d1 = has1 ? dst[e0 + 1] : d0;

    const uint4 u0 =
        reinterpret_cast<const uint4*>(g_u + (size_t)s0 * HIDDEN)[lane];
    const uint4 v0 =
        reinterpret_cast<const uint4*>(g_v + (size_t)d0 * HIDDEN)[lane];
    const uint4 u1 =
        reinterpret_cast<const uint4*>(g_u + (size_t)s1 * HIDDEN)[lane];
    const uint4 v1 =
        reinterpret_cast<const uint4*>(g_v + (size_t)d1 * HIDDEN)[lane];

    const __half2* u0h = reinterpret_cast<const __half2*>(&u0);
    const __half2* v0h = reinterpret_cast<const __half2*>(&v0);
    const __half2* u1h = reinterpret_cast<const __half2*>(&u1);
    const __half2* v1h = reinterpret_cast<const __half2*>(&v1);

    float acc0 = 0.f, acc1 = 0.f;
    #pragma unroll
    for (int i = 0; i < 4; i++) {
        float2 a = __half22float2(u0h[i]);
        float2 b = __half22float2(v0h[i]);
        acc0 = fmaf(fmaxf(a.x + b.x, 0.f), w[2 * i], acc0);
        acc0 = fmaf(fmaxf(a.y + b.y, 0.f), w[2 * i + 1], acc0);
        float2 c = __half22float2(u1h[i]);
        float2 d = __half22float2(v1h[i]);
        acc1 = fmaf(fmaxf(c.x + d.x, 0.f), w[2 * i], acc1);
        acc1 = fmaf(fmaxf(c.y + d.y, 0.f), w[2 * i + 1], acc1);
    }
    #pragma unroll
    for (int o = 16; o > 0; o >>= 1) {
        acc0 += __shfl_xor_sync(0xFFFFFFFFu, acc0, o);
        acc1 += __shfl_xor_sync(0xFFFFFFFFu, acc1, o);
    }

    if (lane == 0) {
        out[e0] = acc0 + bias;
        if (has1) out[e0 + 1] = acc1 + bias;
    }
}

// ---------------------------------------------------------------------------
extern "C" void kernel_launch(void* const* d_in, const int* in_sizes, int n_in,
                              void* d_out, int out_size)
{
    const float* Hs = (const float*)d_in[0];
    const float* Hd = (const float*)d_in[1];
    const int*   src = (const int*)d_in[2];
    const int*   dst = (const int*)d_in[3];
    const float* W1 = (const float*)d_in[4];
    const float* b1 = (const float*)d_in[5];
    const float* W2 = (const float*)d_in[6];
    const float* b2 = (const float*)d_in[7];
    float* out = (float*)d_out;

    const int M = in_sizes[0] / IN_FEATS;
    const int E = in_sizes[2];
    const int nTiles = (M + 63) / 64;

    cudaFuncSetAttribute(node_gemm_persistent,
                         cudaFuncAttributeMaxDynamicSharedMemorySize, SM_TOTAL);

    prep_W<<<128, 256>>>(W1);
    node_gemm_persistent<<<148, 256, SM_TOTAL>>>(Hs, Hd, b1, M, nTiles);
    edge_score_kernel<<<(E + 15) / 16, 256>>>(src, dst, W2, b2, out, E);
}

// round 9
// speedup vs baseline: 3.4741x; 1.0800x over previous
#include <cuda_runtime.h>
#include <cuda_fp16.h>
#include <cstdint>

#define IN_FEATS 128
#define HIDDEN   256
#define NMAX     100000

// fp16 per-node projections: u = Hs@W1a + b1, v = Hd@W1b
__device__ __align__(16) unsigned short g_u[(size_t)NMAX * HIDDEN];
__device__ __align__(16) unsigned short g_v[(size_t)NMAX * HIDDEN];

// W1 fp16 swizzled B images: [isv(2)][n(256)][16 chunks of 16B]
__device__ uint4 g_Wf[2 * 256 * 16];

// ---------------------------------------------------------------------------
// helpers
// ---------------------------------------------------------------------------
__device__ __forceinline__ uint32_t smem_u32(const void* p) {
    uint32_t a;
    asm("{ .reg .u64 t; cvta.to.shared.u64 t, %1; cvt.u32.u64 %0, t; }"
        : "=r"(a) : "l"(p));
    return a;
}
__device__ __forceinline__ void cp_async16(uint32_t dst, const void* src) {
    asm volatile("cp.async.cg.shared.global [%0], [%1], 16;"
                 :: "r"(dst), "l"(src));
}
__device__ __forceinline__ void cp_async16z(uint32_t dst, const void* src,
                                            int srcsz) {
    asm volatile("cp.async.cg.shared.global [%0], [%1], 16, %2;"
                 :: "r"(dst), "l"(src), "r"(srcsz));
}
__device__ __forceinline__ void cp_async_commit() {
    asm volatile("cp.async.commit_group;");
}
__device__ __forceinline__ void cp_async_wait_all() {
    asm volatile("cp.async.wait_group 0;" ::: "memory");
}
__device__ __forceinline__ void ldsm4(uint32_t* r, uint32_t a) {
    asm volatile("ldmatrix.sync.aligned.m8n8.x4.shared.b16 {%0,%1,%2,%3}, [%4];"
                 : "=r"(r[0]), "=r"(r[1]), "=r"(r[2]), "=r"(r[3]) : "r"(a));
}
// m16n8k16 fp16 mma, fp32 accum
__device__ __forceinline__ void mma_f16(float* d, const uint32_t* a,
                                        const uint32_t* b) {
    asm volatile(
        "mma.sync.aligned.m16n8k16.row.col.f32.f16.f16.f32 "
        "{%0,%1,%2,%3}, {%4,%5,%6,%7}, {%8,%9}, {%0,%1,%2,%3};"
        : "+f"(d[0]), "+f"(d[1]), "+f"(d[2]), "+f"(d[3])
        : "r"(a[0]), "r"(a[1]), "r"(a[2]), "r"(a[3]), "r"(b[0]), "r"(b[1]));
}
__device__ __forceinline__ uint32_t pack_h2(float a, float b) {
    __half2 p = __floats2half2_rn(a, b);
    return *reinterpret_cast<uint32_t*>(&p);
}
// row-local XOR swizzle: rows 256B (128 fp16), chunk(16B) ^= (row & 7)
__device__ __forceinline__ uint32_t swz(uint32_t row, uint32_t kbyte) {
    return row * 256u + ((((kbyte >> 4) ^ (row & 7u)) << 4) | (kbyte & 15u));
}

// ---------------------------------------------------------------------------
// prep_W: W1 -> fp16 swizzled B images (one-time, 128KB, L2-resident).
// B[n][k] = W1[isv*128 + k][n], row = 128 fp16 = 16 chunks of 16B.
// ---------------------------------------------------------------------------
__global__ __launch_bounds__(256)
void prep_W(const float* __restrict__ W1)
{
    const int idx = blockIdx.x * 256 + threadIdx.x;
    if (idx >= 2 * 256 * 16) return;
    const int isv = idx >> 12;
    const int n   = (idx >> 4) & 255;
    const int c   = idx & 15;

    uint32_t p[4];
    #pragma unroll
    for (int j = 0; j < 4; j++) {
        const float w0 = W1[(size_t)(isv * 128 + c * 8 + 2 * j) * HIDDEN + n];
        const float w1 = W1[(size_t)(isv * 128 + c * 8 + 2 * j + 1) * HIDDEN + n];
        p[j] = pack_h2(w0, w1);
    }
    const int dst = (isv * 256 + n) * 16 + (c ^ (n & 7));
    g_Wf[dst] = make_uint4(p[0], p[1], p[2], p[3]);
}

// SMEM layout (dynamic):
static constexpr int SM_B  = 0;           // 256 rows x 256B = 64KB
static constexpr int SM_A  = 65536;       // 64 rows x 256B = 16KB
static constexpr int SM_AF = 81920;       // fp32 staging 64 x 528B = 33792
static constexpr int AF_STRIDE = 528;
static constexpr int SM_TOTAL = 115712;

// issue cp.async for fp32 A tile (64 rows x 128 f32), ZFILL beyond M
__device__ __forceinline__ void load_A_async(const float* __restrict__ A,
                                             int M, int bm, uint32_t smb,
                                             int tid)
{
    #pragma unroll
    for (int i = 0; i < 8; i++) {
        const int o   = tid + i * 256;
        const int row = o >> 5;
        const int c   = o & 31;
        const float* src = A + (size_t)(bm + row) * IN_FEATS + c * 4;
        const uint32_t dst = smb + SM_AF + row * AF_STRIDE + c * 16;
        cp_async16z(dst, src, (bm + row < M) ? 16 : 0);
    }
    cp_async_commit();
}

// ---------------------------------------------------------------------------
// Persistent node GEMM (fp16 single pass): one CTA per SM; B loaded once;
// per 64-row tile: prefetched fp32 A -> swizzled fp16, 8 ksteps m16n8k16.
// blockIdx.x & 1 = {u, v}.
// ---------------------------------------------------------------------------
__global__ __launch_bounds__(256, 1)
void node_gemm_persistent(const float* __restrict__ Hs,
                          const float* __restrict__ Hd,
                          const float* __restrict__ b1,
                          int M, int nTiles)
{
    extern __shared__ char smem[];
    __shared__ float sB1[HIDDEN];
    const uint32_t smb = smem_u32(smem);

    const int tid  = threadIdx.x;
    const int wid  = tid >> 5;
    const int lane = tid & 31;

    const bool is_u = (blockIdx.x & 1) == 0;
    const int  cta  = blockIdx.x >> 1;
    const int  nCta = gridDim.x >> 1;
    const float* __restrict__ A = is_u ? Hs : Hd;
    unsigned short* __restrict__ C = is_u ? g_u : g_v;

    // ---- one-time: B image (64KB) + bias + first A tile ----
    {
        const uint4* srcB = g_Wf + (is_u ? 0 : 4096);
        #pragma unroll
        for (int i = 0; i < 16; i++) {
            const int o = tid + i * 256;
            cp_async16(smb + SM_B + o * 16, srcB + o);
        }
        cp_async_commit();
    }
    sB1[tid] = b1[tid];
    if (cta < nTiles) load_A_async(A, M, cta * 64, smb, tid);
    cp_async_wait_all();
    __syncthreads();

    // warp tiling: 2(M) x 4(N64) over 64x256
    const int mbase = (wid >> 2) * 32;
    const int nbase = (wid & 3) * 64;

    const uint32_t rowA  = (uint32_t)(mbase + (lane & 15));
    const uint32_t xorA  = rowA & 7u;
    const uint32_t chA0  = (uint32_t)(lane >> 4);
    const uint32_t baseA = rowA * 256u;

    const uint32_t rowB  = (uint32_t)(nbase + (lane & 7) + ((lane >> 4) << 3));
    const uint32_t xorB  = rowB & 7u;
    const uint32_t chB0  = (uint32_t)((lane >> 3) & 1);
    const uint32_t baseB = rowB * 256u;

    // convert-thread mapping: row tid/4, k-quarter (tid&3)*32
    const int cvRow = tid >> 2;
    const int cvKq  = (tid & 3) * 32;
    const char* cvStage = smem + SM_AF + cvRow * AF_STRIDE;

    for (int t = cta; t < nTiles; t += nCta) {
        const int bm = t * 64;

        // ---- convert fp32 staging -> swizzled fp16 A ----
        #pragma unroll
        for (int j = 0; j < 8; j++) {
            const int k = cvKq + j * 4;
            const float4 x = *reinterpret_cast<const float4*>(cvStage + k * 4);
            uint2 hv;
            hv.x = pack_h2(x.x, x.y);
            hv.y = pack_h2(x.z, x.w);
            const uint32_t o = swz((uint32_t)cvRow, (uint32_t)(k * 2));
            *reinterpret_cast<uint2*>(smem + SM_A + o) = hv;
        }
        __syncthreads();

        // ---- prefetch next A tile (overlaps MMA below) ----
        const int tn = t + nCta;
        if (tn < nTiles) load_A_async(A, M, tn * 64, smb, tid);

        // ---- MMA: 8 ksteps, warp 32M x 64N ----
        float acc[2][8][4];
        #pragma unroll
        for (int mt = 0; mt < 2; mt++)
            #pragma unroll
            for (int nt = 0; nt < 8; nt++)
                #pragma unroll
                for (int q = 0; q < 4; q++) acc[mt][nt][q] = 0.f;

        #pragma unroll
        for (int ks = 0; ks < 8; ks++) {
            const uint32_t aAddr0 =
                smb + SM_A + baseA + (((chA0 + 2u * ks) ^ xorA) << 4);
            const uint32_t bAddr0 =
                smb + SM_B + baseB + (((chB0 + 2u * ks) ^ xorB) << 4);
            uint32_t af[2][4], bf[4][4];
            #pragma unroll
            for (int mt = 0; mt < 2; mt++)
                ldsm4(af[mt], aAddr0 + mt * 16 * 256);
            #pragma unroll
            for (int bt = 0; bt < 4; bt++)
                ldsm4(bf[bt], bAddr0 + bt * 16 * 256);
            #pragma unroll
            for (int mt = 0; mt < 2; mt++)
                #pragma unroll
                for (int bt = 0; bt < 4; bt++) {
                    mma_f16(acc[mt][2 * bt],     af[mt], &bf[bt][0]);
                    mma_f16(acc[mt][2 * bt + 1], af[mt], &bf[bt][2]);
                }
        }

        // ---- epilogue: +bias (u only), fp16 pack, store ----
        #pragma unroll
        for (int mt = 0; mt < 2; mt++) {
            const int m0 = mbase + mt * 16 + (lane >> 2);
            #pragma unroll
            for (int half = 0; half < 2; half++) {
                const int grow = bm + m0 + half * 8;
                if (grow >= M) continue;
                unsigned short* orow = C + (size_t)grow * HIDDEN;
                #pragma unroll
                for (int nt = 0; nt < 8; nt++) {
                    const int n = nbase + nt * 8 + (lane & 3) * 2;
                    float f0 = acc[mt][nt][2 * half];
                    float f1 = acc[mt][nt][2 * half + 1];
                    if (is_u) { f0 += sB1[n]; f1 += sB1[n + 1]; }
                    *reinterpret_cast<uint32_t*>(orow + n) = pack_h2(f0, f1);
                }
            }
        }

        cp_async_wait_all();    // next fp32 A tile landed
        __syncthreads();        // epilogue/ldsm done before next convert
    }
}

// ---------------------------------------------------------------------------
// Edge pass (r4-verified): full warp per edge, 2 edges per warp.
// ---------------------------------------------------------------------------
__global__ __launch_bounds__(256)
void edge_score_kernel(const int* __restrict__ src,
                       const int* __restrict__ dst,
                       const float* __restrict__ W2,
                       const float* __restrict__ b2,
                       float* __restrict__ out,
                       int E)
{
    __shared__ float sW2[HIDDEN];
    const int tid = threadIdx.x;
    sW2[tid] = W2[tid];
    __syncthreads();

    const int lane = tid & 31;
    const int warp = tid >> 5;

    const float4 wA = *reinterpret_cast<const float4*>(&sW2[lane * 8]);
    const float4 wB = *reinterpret_cast<const float4*>(&sW2[lane * 8 + 4]);
    const float w[8] = {wA.x, wA.y, wA.z, wA.w, wB.x, wB.y, wB.z, wB.w};
    const float bias = b2[0];

    const int e0 = (blockIdx.x * 8 + warp) * 2;
    if (e0 >= E) return;
    const bool has1 = (e0 + 1) < E;

    const int s0 = src[e0];
    const int d0 = dst[e0];
    const int s1 = has1 ? src[e0 + 1] : s0;
    const int d1 = has1 ? dst[e0 + 1] : d0;

    const uint4 u0 =
        reinterpret_cast<const uint4*>(g_u + (size_t)s0 * HIDDEN)[lane];
    const uint4 v0 =
        reinterpret_cast<const uint4*>(g_v + (size_t)d0 * HIDDEN)[lane];
    const uint4 u1 =
        reinterpret_cast<const uint4*>(g_u + (size_t)s1 * HIDDEN)[lane];
    const uint4 v1 =
        reinterpret_cast<const uint4*>(g_v + (size_t)d1 * HIDDEN)[lane];

    const __half2* u0h = reinterpret_cast<const __half2*>(&u0);
    const __half2* v0h = reinterpret_cast<const __half2*>(&v0);
    const __half2* u1h = reinterpret_cast<const __half2*>(&u1);
    const __half2* v1h = reinterpret_cast<const __half2*>(&v1);

    float acc0 = 0.f, acc1 = 0.f;
    #pragma unroll
    for (int i = 0; i < 4; i++) {
        float2 a = __half22float2(u0h[i]);
        float2 b = __half22float2(v0h[i]);
        acc0 = fmaf(fmaxf(a.x + b.x, 0.f), w[2 * i], acc0);
        acc0 = fmaf(fmaxf(a.y + b.y, 0.f), w[2 * i + 1], acc0);
        float2 c = __half22float2(u1h[i]);
        float2 d = __half22float2(v1h[i]);
        acc1 = fmaf(fmaxf(c.x + d.x, 0.f), w[2 * i], acc1);
        acc1 = fmaf(fmaxf(c.y + d.y, 0.f), w[2 * i + 1], acc1);
    }
    #pragma unroll
    for (int o = 16; o > 0; o >>= 1) {
        acc0 += __shfl_xor_sync(0xFFFFFFFFu, acc0, o);
        acc1 += __shfl_xor_sync(0xFFFFFFFFu, acc1, o);
    }

    if (lane == 0) {
        out[e0] = acc0 + bias;
        if (has1) out[e0 + 1] = acc1 + bias;
    }
}

// ---------------------------------------------------------------------------
extern "C" void kernel_launch(void* const* d_in, const int* in_sizes, int n_in,
                              void* d_out, int out_size)
{
    const float* Hs = (const float*)d_in[0];
    const float* Hd = (const float*)d_in[1];
    const int*   src = (const int*)d_in[2];
    const int*   dst = (const int*)d_in[3];
    const float* W1 = (const float*)d_in[4];
    const float* b1 = (const float*)d_in[5];
    const float* W2 = (const float*)d_in[6];
    const float* b2 = (const float*)d_in[7];
    float* out = (float*)d_out;

    const int M = in_sizes[0] / IN_FEATS;
    const int E = in_sizes[2];
    const int nTiles = (M + 63) / 64;

    cudaFuncSetAttribute(node_gemm_persistent,
                         cudaFuncAttributeMaxDynamicSharedMemorySize, SM_TOTAL);

    prep_W<<<32, 256>>>(W1);
    node_gemm_persistent<<<148, 256, SM_TOTAL>>>(Hs, Hd, b1, M, nTiles);
    edge_score_kernel<<<(E + 15) / 16, 256>>>(src, dst, W2, b2, out, E);
}